// round 15
// baseline (speedup 1.0000x reference)
#include <cuda_runtime.h>
#include <math.h>
#include <stdint.h>

// ---------------------------------------------------------------------------
// MultilayerGRU  B=64 S=1024 I=128 H=512 L=3 O=128
// Persistent cooperative kernel, 128 CTAs x 1024 threads (occ 50%).
// Thread (q=tid>>6, b=tid&63) computes K-partial dots for ALL 4 of this CTA's
// output columns over k-slice q (1/16 of K), packed fp32x2 FMAs, 16-deep SMEM
// reduction. 6 grid barriers per timestep.
// ---------------------------------------------------------------------------

#define NCTA 128
#define NTHR 1024
#define Bx   64
#define Sx   1024
#define Ix   128
#define Hx   512
#define Lx   3
#define Ox   128
#define CPT  4
#define HQ   (Hx/4)     // 128 float4 per activation row
#define IQ   (Ix/4)     // 32

// ---- shared memory layout (float offsets) ----
#define WHZ0 0
#define WHR0 2048
#define WHG0 4096
#define WX0Z 6144
#define WX0R 6656
#define WX0G 7168
#define WXZ1 7680
#define WXR1 9728
#define WXG1 11776
#define WHZ1 13824
#define WHR1 15872
#define WHG1 17920
#define WXZ2 19968
#define WXR2 22016
#define WXG2 24064
#define WHZ2 26112
#define WHR2 28160
#define WHG2 30208
#define WYOF 32256
#define SM_RED 32768            // 16 q * 16 slots * 64 b = 16384 floats
#define SM_BZ  49152
#define SM_BR  49168
#define SM_BG  49184
#define SM_BY  49200
#define SMEM_FLOATS 49216
#define SMEM_BYTES  (SMEM_FLOATS * 4)

// ---- global scratch ----
__device__ float4 g_x0t[(size_t)Sx * IQ * Bx];   // [s][j4][b]
__device__ float4 g_h[Lx * HQ * Bx];             // [l][k4][b]
__device__ float4 g_rh[HQ * Bx];                 // [k4][b]
__device__ unsigned g_bar;

// ---------------------------------------------------------------------------
__device__ __forceinline__ unsigned long long pfma(unsigned long long a,
                                                   unsigned long long b,
                                                   unsigned long long c) {
    unsigned long long d;
    asm("fma.rn.f32x2 %0, %1, %2, %3;" : "=l"(d) : "l"(a), "l"(b), "l"(c));
    return d;
}

__device__ __forceinline__ float phsum(unsigned long long v) {
    float lo = __uint_as_float((unsigned)(v & 0xffffffffULL));
    float hi = __uint_as_float((unsigned)(v >> 32));
    return lo + hi;
}

__device__ __forceinline__ float fsigm(float x) {
    return __fdividef(1.f, 1.f + __expf(-x));
}
__device__ __forceinline__ float ftanh(float x) {
    float e = __expf(-2.f * x);
    return __fdividef(1.f - e, 1.f + e);
}

__device__ __forceinline__ void gbar(unsigned target) {
    __syncthreads();
    if (threadIdx.x == 0) {
        unsigned* p = &g_bar;
        asm volatile("red.release.gpu.global.add.u32 [%0], 1;" :: "l"(p) : "memory");
        unsigned v;
        do {
            asm volatile("ld.acquire.gpu.global.u32 %0, [%1];" : "=r"(v) : "l"(p) : "memory");
        } while (v < target);
    }
    __syncthreads();
}

// ---------------------------------------------------------------------------
// Phase-1 partials: z/r over h, z/r/g over x, for all 4 columns, k-slice q.
// h-slice: 4..4+? -> 8 float4 iters at base q*8; x-slice: XKPT iters at q*XKPT.
template<int XKPT, int XSTR>
__device__ __forceinline__ void p1_partials(
    float* sw, int b, int q,
    const ulonglong2* __restrict__ hsrc,
    const ulonglong2* __restrict__ xsrc,
    int whz, int whr, int wxz, int wxr, int wxg)
{
    const ulonglong2* wz2 = (const ulonglong2*)(sw + whz);
    const ulonglong2* wr2 = (const ulonglong2*)(sw + whr);
    const ulonglong2* xz2 = (const ulonglong2*)(sw + wxz);
    const ulonglong2* xr2 = (const ulonglong2*)(sw + wxr);
    const ulonglong2* xg2 = (const ulonglong2*)(sw + wxg);

    unsigned long long az[4], ar[4], ag[4];
#pragma unroll
    for (int cp = 0; cp < 4; cp++) { az[cp] = 0ULL; ar[cp] = 0ULL; ag[cp] = 0ULL; }

    const int k0 = q * 8;
#pragma unroll
    for (int k4 = k0; k4 < k0 + 8; k4++) {
        ulonglong2 hv = hsrc[k4 * Bx + b];
#pragma unroll
        for (int cp = 0; cp < 4; cp++) {
            ulonglong2 w1 = wz2[cp * 128 + k4];
            ulonglong2 w2 = wr2[cp * 128 + k4];
            az[cp] = pfma(hv.x, w1.x, az[cp]);
            ar[cp] = pfma(hv.x, w2.x, ar[cp]);
            az[cp] = pfma(hv.y, w1.y, az[cp]);
            ar[cp] = pfma(hv.y, w2.y, ar[cp]);
        }
    }

    const int j0 = q * XKPT;
#pragma unroll
    for (int j4 = j0; j4 < j0 + XKPT; j4++) {
        ulonglong2 xv = xsrc[j4 * Bx + b];
#pragma unroll
        for (int cp = 0; cp < 4; cp++) {
            ulonglong2 w1 = xz2[cp * XSTR + j4];
            ulonglong2 w2 = xr2[cp * XSTR + j4];
            ulonglong2 w3 = xg2[cp * XSTR + j4];
            az[cp] = pfma(xv.x, w1.x, az[cp]);
            ar[cp] = pfma(xv.x, w2.x, ar[cp]);
            ag[cp] = pfma(xv.x, w3.x, ag[cp]);
            az[cp] = pfma(xv.y, w1.y, az[cp]);
            ar[cp] = pfma(xv.y, w2.y, ar[cp]);
            ag[cp] = pfma(xv.y, w3.y, ag[cp]);
        }
    }

#pragma unroll
    for (int cp = 0; cp < 4; cp++) {
        sw[SM_RED + (q * 16 + cp)     * Bx + b] = phsum(az[cp]);
        sw[SM_RED + (q * 16 + 4 + cp) * Bx + b] = phsum(ar[cp]);
        sw[SM_RED + (q * 16 + 8 + cp) * Bx + b] = phsum(ag[cp]);
    }
}

// Phase-1 finalize (after __syncthreads): threads tid<256 (q<4) own column c=q.
__device__ __forceinline__ void p1_final(
    float* sw, int b, int q, int cta, int l,
    const float* __restrict__ hbase,
    float& z_reg, float& xg_reg)
{
    if (q >= 4) return;
    const int c = q;
    float sz = 0.f, sr = 0.f, sg = 0.f;
#pragma unroll
    for (int qq = 0; qq < 16; qq++) {
        sz += sw[SM_RED + (qq * 16 + c)     * Bx + b];
        sr += sw[SM_RED + (qq * 16 + 4 + c) * Bx + b];
        sg += sw[SM_RED + (qq * 16 + 8 + c) * Bx + b];
    }
    float z = fsigm(sz + sw[SM_BZ + l * 4 + c]);
    float r = fsigm(sr + sw[SM_BR + l * 4 + c]);
    z_reg  = z;
    xg_reg = sg + sw[SM_BG + l * 4 + c];
    float hcur = hbase[(cta * Bx + b) * 4 + c];
    ((float*)g_rh)[(cta * Bx + b) * 4 + c] = r * hcur;
}

// Phase-2 partials: g-dot over rh for all 4 columns, k-slice q.
__device__ __forceinline__ void p2_partials(float* sw, int b, int q, int whg)
{
    const ulonglong2* wg2 = (const ulonglong2*)(sw + whg);
    const ulonglong2* rh2 = (const ulonglong2*)g_rh;
    unsigned long long a[4] = {0ULL, 0ULL, 0ULL, 0ULL};
    const int k0 = q * 8;
#pragma unroll
    for (int k4 = k0; k4 < k0 + 8; k4++) {
        ulonglong2 rv = rh2[k4 * Bx + b];
#pragma unroll
        for (int cp = 0; cp < 4; cp++) {
            ulonglong2 w = wg2[cp * 128 + k4];
            a[cp] = pfma(rv.x, w.x, a[cp]);
            a[cp] = pfma(rv.y, w.y, a[cp]);
        }
    }
#pragma unroll
    for (int cp = 0; cp < 4; cp++)
        sw[SM_RED + (q * 16 + cp) * Bx + b] = phsum(a[cp]);
}

__device__ __forceinline__ void p2_final(
    float* sw, int b, int q, int cta, int l, float z_reg, float xg_reg)
{
    if (q >= 4) return;
    const int c = q;
    float s = 0.f;
#pragma unroll
    for (int qq = 0; qq < 16; qq++)
        s += sw[SM_RED + (qq * 16 + c) * Bx + b];
    float g = ftanh(s + xg_reg);
    float* hp = ((float*)g_h) + (((size_t)l * HQ + cta) * Bx + b) * 4 + c;
    float hold = *hp;
    *hp = fmaf(z_reg, hold - g, g);
}

// Output-projection partial over h2 (folded into P01 of step t+1).
__device__ __forceinline__ void y_partial(float* sw, int b, int q)
{
    const ulonglong2* h2  = (const ulonglong2*)(g_h + 2 * HQ * Bx);
    const ulonglong2* wy2 = (const ulonglong2*)(sw + WYOF);
    unsigned long long ay = 0ULL;
    const int k0 = q * 8;
#pragma unroll
    for (int k4 = k0; k4 < k0 + 8; k4++) {
        ulonglong2 hv = h2[k4 * Bx + b];
        ulonglong2 w  = wy2[k4];
        ay = pfma(hv.x, w.x, ay);
        ay = pfma(hv.y, w.y, ay);
    }
    sw[SM_RED + (q * 16 + 12) * Bx + b] = phsum(ay);
}

// Finalize y: threads with q==4 (tid 256..319), one b each.
__device__ __forceinline__ void y_final(float* sw, int b, int cta,
                                        float* __restrict__ out, int tdst)
{
    float s = 0.f;
#pragma unroll
    for (int qq = 0; qq < 16; qq++)
        s += sw[SM_RED + (qq * 16 + 12) * Bx + b];
    out[((size_t)b * Sx + tdst) * Ox + cta] = s + sw[SM_BY];
}

// ---------------------------------------------------------------------------
__global__ void init_kernel(const float* __restrict__ in, const float* __restrict__ hs)
{
    size_t i = (size_t)blockIdx.x * blockDim.x + threadIdx.x;
    size_t stride = (size_t)gridDim.x * blockDim.x;
    if (i == 0) g_bar = 0;

    for (size_t idx = i; idx < (size_t)Bx * Lx * Hx; idx += stride) {
        int b = (int)(idx / (Lx * Hx));
        int l = (int)((idx / Hx) % Lx);
        int k = (int)(idx % Hx);
        ((float*)g_h)[(((size_t)l * HQ + (k >> 2)) * Bx + b) * 4 + (k & 3)] = hs[idx];
    }
    for (size_t idx = i; idx < (size_t)Bx * Sx * Ix; idx += stride) {
        int b = (int)(idx / ((size_t)Sx * Ix));
        int s = (int)((idx / Ix) % Sx);
        int j = (int)(idx % Ix);
        ((float*)g_x0t)[(((size_t)s * IQ + (j >> 2)) * Bx + b) * 4 + (j & 3)] = in[idx];
    }
}

__global__ void __launch_bounds__(NTHR, 1) gru_main(
    const float* __restrict__ Wx0z, const float* __restrict__ Wx0r, const float* __restrict__ Wx0g,
    const float* __restrict__ Wxz,  const float* __restrict__ Wxr,  const float* __restrict__ Wxg,
    const float* __restrict__ Whz,  const float* __restrict__ Whr,  const float* __restrict__ Whg,
    const float* __restrict__ bz,   const float* __restrict__ br,   const float* __restrict__ bg,
    const float* __restrict__ Wy,   const float* __restrict__ by,
    float* __restrict__ out)
{
    extern __shared__ float sw[];
    const int tid = threadIdx.x;
    const int cta = blockIdx.x;
    const int nb  = cta * CPT;

    // ---- load this CTA's weight slices into SMEM (once) ----
    for (int i = tid; i < CPT * Hx; i += NTHR) {
        int cp = i >> 9, k = i & 511;
        int row = nb + cp;
        sw[WHZ0 + i] = Whz[((size_t)(0 * Hx + row)) * Hx + k];
        sw[WHR0 + i] = Whr[((size_t)(0 * Hx + row)) * Hx + k];
        sw[WHG0 + i] = Whg[((size_t)(0 * Hx + row)) * Hx + k];
        sw[WHZ1 + i] = Whz[((size_t)(1 * Hx + row)) * Hx + k];
        sw[WHR1 + i] = Whr[((size_t)(1 * Hx + row)) * Hx + k];
        sw[WHG1 + i] = Whg[((size_t)(1 * Hx + row)) * Hx + k];
        sw[WHZ2 + i] = Whz[((size_t)(2 * Hx + row)) * Hx + k];
        sw[WHR2 + i] = Whr[((size_t)(2 * Hx + row)) * Hx + k];
        sw[WHG2 + i] = Whg[((size_t)(2 * Hx + row)) * Hx + k];
        sw[WXZ1 + i] = Wxz[((size_t)(0 * Hx + row)) * Hx + k];
        sw[WXR1 + i] = Wxr[((size_t)(0 * Hx + row)) * Hx + k];
        sw[WXG1 + i] = Wxg[((size_t)(0 * Hx + row)) * Hx + k];
        sw[WXZ2 + i] = Wxz[((size_t)(1 * Hx + row)) * Hx + k];
        sw[WXR2 + i] = Wxr[((size_t)(1 * Hx + row)) * Hx + k];
        sw[WXG2 + i] = Wxg[((size_t)(1 * Hx + row)) * Hx + k];
    }
    for (int i = tid; i < CPT * Ix; i += NTHR) {
        int cp = i >> 7, j = i & 127;
        int row = nb + cp;
        sw[WX0Z + i] = Wx0z[(size_t)row * Ix + j];
        sw[WX0R + i] = Wx0r[(size_t)row * Ix + j];
        sw[WX0G + i] = Wx0g[(size_t)row * Ix + j];
    }
    for (int i = tid; i < Hx; i += NTHR)
        sw[WYOF + i] = Wy[(size_t)cta * Hx + i];
    if (tid < 12) {
        int l = tid >> 2, cp = tid & 3;
        sw[SM_BZ + tid] = bz[l * Hx + nb + cp];
        sw[SM_BR + tid] = br[l * Hx + nb + cp];
        sw[SM_BG + tid] = bg[l * Hx + nb + cp];
    }
    if (tid == 0) sw[SM_BY] = by[cta];
    __syncthreads();

    const int b = tid & 63;
    const int q = tid >> 6;     // 16 k-slices

    const ulonglong2* h0u = (const ulonglong2*)(g_h);
    const ulonglong2* h1u = (const ulonglong2*)(g_h + 1 * HQ * Bx);
    const ulonglong2* h2u = (const ulonglong2*)(g_h + 2 * HQ * Bx);

    float z_reg = 0.f, xg_reg = 0.f;
    unsigned bv = 0;

    for (int t = 0; t < Sx; t++) {
        const ulonglong2* xt = (const ulonglong2*)(g_x0t + (size_t)t * IQ * Bx);

        // P(0,1): layer-0 z/r/xg + y for step t-1 (h2 still holds step t-1)
        p1_partials<2, 32>(sw, b, q, h0u, xt, WHZ0, WHR0, WX0Z, WX0R, WX0G);
        if (t > 0) y_partial(sw, b, q);
        __syncthreads();
        p1_final(sw, b, q, cta, 0, (const float*)g_h, z_reg, xg_reg);
        if (t > 0 && q == 4) y_final(sw, b, cta, out, t - 1);
        bv++; gbar(bv * NCTA);

        // P(0,2)
        p2_partials(sw, b, q, WHG0);
        __syncthreads();
        p2_final(sw, b, q, cta, 0, z_reg, xg_reg);
        bv++; gbar(bv * NCTA);

        // P(1,1): x = new h0
        p1_partials<8, 128>(sw, b, q, h1u, h0u, WHZ1, WHR1, WXZ1, WXR1, WXG1);
        __syncthreads();
        p1_final(sw, b, q, cta, 1, (const float*)(g_h + HQ * Bx), z_reg, xg_reg);
        bv++; gbar(bv * NCTA);

        // P(1,2)
        p2_partials(sw, b, q, WHG1);
        __syncthreads();
        p2_final(sw, b, q, cta, 1, z_reg, xg_reg);
        bv++; gbar(bv * NCTA);

        // P(2,1): x = new h1
        p1_partials<8, 128>(sw, b, q, h2u, h1u, WHZ2, WHR2, WXZ2, WXR2, WXG2);
        __syncthreads();
        p1_final(sw, b, q, cta, 2, (const float*)(g_h + 2 * HQ * Bx), z_reg, xg_reg);
        bv++; gbar(bv * NCTA);

        // P(2,2)
        p2_partials(sw, b, q, WHG2);
        __syncthreads();
        p2_final(sw, b, q, cta, 2, z_reg, xg_reg);
        bv++; gbar(bv * NCTA);
    }

    // y for the final timestep
    y_partial(sw, b, q);
    __syncthreads();
    if (q == 4) y_final(sw, b, cta, out, Sx - 1);

    // hidden_out (B, L, H)
    if (q < 4) {
        const int c = q;
#pragma unroll
        for (int l = 0; l < Lx; l++) {
            float hv = ((const float*)g_h)[(((size_t)l * HQ + cta) * Bx + b) * 4 + c];
            out[(size_t)Bx * Sx * Ox + ((size_t)b * Lx + l) * Hx + nb + c] = hv;
        }
    }
}

// ---------------------------------------------------------------------------
extern "C" void kernel_launch(void* const* d_in, const int* in_sizes, int n_in,
                              void* d_out, int out_size)
{
    const float* input = (const float*)d_in[0];
    const float* hs    = (const float*)d_in[1];
    const float* Wx0z  = (const float*)d_in[2];
    const float* Wx0r  = (const float*)d_in[3];
    const float* Wx0g  = (const float*)d_in[4];
    const float* Wxz   = (const float*)d_in[5];
    const float* Wxr   = (const float*)d_in[6];
    const float* Wxg   = (const float*)d_in[7];
    const float* Whz   = (const float*)d_in[8];
    const float* Whr   = (const float*)d_in[9];
    const float* Whg   = (const float*)d_in[10];
    const float* bz    = (const float*)d_in[11];
    const float* br    = (const float*)d_in[12];
    const float* bg    = (const float*)d_in[13];
    const float* Wy    = (const float*)d_in[14];
    const float* by    = (const float*)d_in[15];
    float* out = (float*)d_out;

    cudaFuncSetAttribute(gru_main, cudaFuncAttributeMaxDynamicSharedMemorySize, SMEM_BYTES);

    init_kernel<<<1024, 256>>>(input, hs);
    gru_main<<<NCTA, NTHR, SMEM_BYTES>>>(Wx0z, Wx0r, Wx0g, Wxz, Wxr, Wxg,
                                         Whz, Whr, Whg, bz, br, bg, Wy, by, out);
}

// round 16
// speedup vs baseline: 1.4339x; 1.4339x over previous
#include <cuda_runtime.h>
#include <math.h>
#include <stdint.h>

// ---------------------------------------------------------------------------
// MultilayerGRU  B=64 S=1024 I=128 H=512 L=3 O=128
// Persistent cooperative kernel, 128 CTAs x 512 threads (R13 shape).
// Thread (q=tid>>5, lane=tid&31) handles b={lane,lane+32}, k-slice q (1/16 K),
// all 4 CTA output columns, packed fp32x2 FMAs, 16-deep SMEM reduction.
// NEW: split grid barrier (arrive/wait) with dependency-safe compute overlap
// hiding 4 of the 6 barrier waits per timestep.
// ---------------------------------------------------------------------------

#define NCTA 128
#define NTHR 512
#define Bx   64
#define Sx   1024
#define Ix   128
#define Hx   512
#define Lx   3
#define Ox   128
#define CPT  4
#define HQ   (Hx/4)     // 128 float4 per activation row
#define IQ   (Ix/4)     // 32

// ---- shared memory layout (float offsets) ----
#define WHZ0 0
#define WHR0 2048
#define WHG0 4096
#define WX0Z 6144
#define WX0R 6656
#define WX0G 7168
#define WXZ1 7680
#define WXR1 9728
#define WXG1 11776
#define WHZ1 13824
#define WHR1 15872
#define WHG1 17920
#define WXZ2 19968
#define WXR2 22016
#define WXG2 24064
#define WHZ2 26112
#define WHR2 28160
#define WHG2 30208
#define WYOF 32256
#define SM_RED 32768            // 16 q * 16 slots * 64 b
#define SM_BZ  49152
#define SM_BR  49168
#define SM_BG  49184
#define SM_BY  49200
#define SMEM_FLOATS 49216
#define SMEM_BYTES  (SMEM_FLOATS * 4)

// ---- global scratch ----
__device__ float4 g_x0t[(size_t)Sx * IQ * Bx];   // [s][j4][b]
__device__ float4 g_h[Lx * HQ * Bx];             // [l][k4][b]
__device__ float4 g_rh[HQ * Bx];                 // [k4][b]
__device__ unsigned g_bar;

// ---------------------------------------------------------------------------
__device__ __forceinline__ unsigned long long pfma(unsigned long long a,
                                                   unsigned long long b,
                                                   unsigned long long c) {
    unsigned long long d;
    asm("fma.rn.f32x2 %0, %1, %2, %3;" : "=l"(d) : "l"(a), "l"(b), "l"(c));
    return d;
}

__device__ __forceinline__ float phsum(unsigned long long v) {
    float lo = __uint_as_float((unsigned)(v & 0xffffffffULL));
    float hi = __uint_as_float((unsigned)(v >> 32));
    return lo + hi;
}

__device__ __forceinline__ float fsigm(float x) {
    return __fdividef(1.f, 1.f + __expf(-x));
}
__device__ __forceinline__ float ftanh(float x) {
    float e = __expf(-2.f * x);
    return __fdividef(1.f - e, 1.f + e);
}

// Split grid barrier: arrive (release) / wait (acquire poll).
__device__ __forceinline__ void gbar_arrive() {
    __syncthreads();
    if (threadIdx.x == 0) {
        unsigned* p = &g_bar;
        asm volatile("red.release.gpu.global.add.u32 [%0], 1;" :: "l"(p) : "memory");
    }
}
__device__ __forceinline__ void gbar_wait(unsigned target) {
    if (threadIdx.x == 0) {
        unsigned* p = &g_bar;
        unsigned v;
        do {
            asm volatile("ld.acquire.gpu.global.u32 %0, [%1];" : "=r"(v) : "l"(p) : "memory");
        } while (v < target);
    }
    __syncthreads();
}

// ---------------------------------------------------------------------------
// Accumulating dot helpers: R=2 b-values (b0, b0+32), 4 columns, NIT float4.
template<int NIT>
__device__ __forceinline__ void dacc2(
    unsigned long long az[2][4], unsigned long long ar[2][4],
    const ulonglong2* __restrict__ src, int k0, int b0,
    const ulonglong2* __restrict__ w1, const ulonglong2* __restrict__ w2,
    int wstr)
{
#pragma unroll
    for (int i = 0; i < NIT; i++) {
        const int k4 = k0 + i;
        ulonglong2 h0 = src[k4 * Bx + b0];
        ulonglong2 h1 = src[k4 * Bx + b0 + 32];
#pragma unroll
        for (int cp = 0; cp < 4; cp++) {
            ulonglong2 wz = w1[cp * wstr + k4];
            ulonglong2 wr = w2[cp * wstr + k4];
            az[0][cp] = pfma(h0.x, wz.x, az[0][cp]);
            az[1][cp] = pfma(h1.x, wz.x, az[1][cp]);
            ar[0][cp] = pfma(h0.x, wr.x, ar[0][cp]);
            ar[1][cp] = pfma(h1.x, wr.x, ar[1][cp]);
            az[0][cp] = pfma(h0.y, wz.y, az[0][cp]);
            az[1][cp] = pfma(h1.y, wz.y, az[1][cp]);
            ar[0][cp] = pfma(h0.y, wr.y, ar[0][cp]);
            ar[1][cp] = pfma(h1.y, wr.y, ar[1][cp]);
        }
    }
}

template<int NIT>
__device__ __forceinline__ void dacc3(
    unsigned long long az[2][4], unsigned long long ar[2][4],
    unsigned long long ag[2][4],
    const ulonglong2* __restrict__ src, int k0, int b0,
    const ulonglong2* __restrict__ w1, const ulonglong2* __restrict__ w2,
    const ulonglong2* __restrict__ w3, int wstr)
{
#pragma unroll
    for (int i = 0; i < NIT; i++) {
        const int k4 = k0 + i;
        ulonglong2 x0 = src[k4 * Bx + b0];
        ulonglong2 x1 = src[k4 * Bx + b0 + 32];
#pragma unroll
        for (int cp = 0; cp < 4; cp++) {
            ulonglong2 wz = w1[cp * wstr + k4];
            ulonglong2 wr = w2[cp * wstr + k4];
            ulonglong2 wg = w3[cp * wstr + k4];
            az[0][cp] = pfma(x0.x, wz.x, az[0][cp]);
            az[1][cp] = pfma(x1.x, wz.x, az[1][cp]);
            ar[0][cp] = pfma(x0.x, wr.x, ar[0][cp]);
            ar[1][cp] = pfma(x1.x, wr.x, ar[1][cp]);
            ag[0][cp] = pfma(x0.x, wg.x, ag[0][cp]);
            ag[1][cp] = pfma(x1.x, wg.x, ag[1][cp]);
            az[0][cp] = pfma(x0.y, wz.y, az[0][cp]);
            az[1][cp] = pfma(x1.y, wz.y, az[1][cp]);
            ar[0][cp] = pfma(x0.y, wr.y, ar[0][cp]);
            ar[1][cp] = pfma(x1.y, wr.y, ar[1][cp]);
            ag[0][cp] = pfma(x0.y, wg.y, ag[0][cp]);
            ag[1][cp] = pfma(x1.y, wg.y, ag[1][cp]);
        }
    }
}

template<int NIT>
__device__ __forceinline__ void dacc1(
    unsigned long long a[2][4],
    const ulonglong2* __restrict__ src, int k0, int b0,
    const ulonglong2* __restrict__ w, int wstr)
{
#pragma unroll
    for (int i = 0; i < NIT; i++) {
        const int k4 = k0 + i;
        ulonglong2 r0 = src[k4 * Bx + b0];
        ulonglong2 r1 = src[k4 * Bx + b0 + 32];
#pragma unroll
        for (int cp = 0; cp < 4; cp++) {
            ulonglong2 wg = w[cp * wstr + k4];
            a[0][cp] = pfma(r0.x, wg.x, a[0][cp]);
            a[1][cp] = pfma(r1.x, wg.x, a[1][cp]);
            a[0][cp] = pfma(r0.y, wg.y, a[0][cp]);
            a[1][cp] = pfma(r1.y, wg.y, a[1][cp]);
        }
    }
}

__device__ __forceinline__ void zero24(unsigned long long az[2][4],
                                       unsigned long long ar[2][4],
                                       unsigned long long ag[2][4]) {
#pragma unroll
    for (int r = 0; r < 2; r++)
#pragma unroll
        for (int cp = 0; cp < 4; cp++) { az[r][cp] = 0ULL; ar[r][cp] = 0ULL; ag[r][cp] = 0ULL; }
}
__device__ __forceinline__ void zero8(unsigned long long a[2][4]) {
#pragma unroll
    for (int r = 0; r < 2; r++)
#pragma unroll
        for (int cp = 0; cp < 4; cp++) a[r][cp] = 0ULL;
}

__device__ __forceinline__ void store_zrg(float* sw, int q, int b0,
    unsigned long long az[2][4], unsigned long long ar[2][4],
    unsigned long long ag[2][4])
{
#pragma unroll
    for (int r = 0; r < 2; r++) {
        int b = b0 + 32 * r;
#pragma unroll
        for (int cp = 0; cp < 4; cp++) {
            sw[SM_RED + (q * 16 + cp)     * Bx + b] = phsum(az[r][cp]);
            sw[SM_RED + (q * 16 + 4 + cp) * Bx + b] = phsum(ar[r][cp]);
            sw[SM_RED + (q * 16 + 8 + cp) * Bx + b] = phsum(ag[r][cp]);
        }
    }
}

__device__ __forceinline__ void store_g(float* sw, int q, int b0,
                                        unsigned long long a[2][4])
{
#pragma unroll
    for (int r = 0; r < 2; r++) {
        int b = b0 + 32 * r;
#pragma unroll
        for (int cp = 0; cp < 4; cp++)
            sw[SM_RED + (q * 16 + cp) * Bx + b] = phsum(a[r][cp]);
    }
}

// Phase-1 finalize: warps q<4 own column c=q; lanes handle b=lane, lane+32.
__device__ __forceinline__ void p1_final(
    float* sw, int lane, int q, int cta, int l,
    const float* __restrict__ hbase,
    float2& z_reg, float2& xg_reg)
{
    if (q >= 4) return;
    const int c = q;
    float zz[2], xx[2];
#pragma unroll
    for (int r = 0; r < 2; r++) {
        const int b = lane + 32 * r;
        float sz = 0.f, sr = 0.f, sg = 0.f;
#pragma unroll
        for (int qq = 0; qq < 16; qq++) {
            sz += sw[SM_RED + (qq * 16 + c)     * Bx + b];
            sr += sw[SM_RED + (qq * 16 + 4 + c) * Bx + b];
            sg += sw[SM_RED + (qq * 16 + 8 + c) * Bx + b];
        }
        float z  = fsigm(sz + sw[SM_BZ + l * 4 + c]);
        float rr = fsigm(sr + sw[SM_BR + l * 4 + c]);
        zz[r] = z;
        xx[r] = sg + sw[SM_BG + l * 4 + c];
        float hcur = hbase[(cta * Bx + b) * 4 + c];
        ((float*)g_rh)[(cta * Bx + b) * 4 + c] = rr * hcur;
    }
    z_reg  = make_float2(zz[0], zz[1]);
    xg_reg = make_float2(xx[0], xx[1]);
}

__device__ __forceinline__ void p2_final(
    float* sw, int lane, int q, int cta, int l, float2 z_reg, float2 xg_reg)
{
    if (q >= 4) return;
    const int c = q;
#pragma unroll
    for (int r = 0; r < 2; r++) {
        const int b = lane + 32 * r;
        float s = 0.f;
#pragma unroll
        for (int qq = 0; qq < 16; qq++)
            s += sw[SM_RED + (qq * 16 + c) * Bx + b];
        float xg = (r == 0) ? xg_reg.x : xg_reg.y;
        float z  = (r == 0) ? z_reg.x  : z_reg.y;
        float g = ftanh(s + xg);
        float* hp = ((float*)g_h) + (((size_t)l * HQ + cta) * Bx + b) * 4 + c;
        float hold = *hp;
        *hp = fmaf(z, hold - g, g);
    }
}

// Output-projection partial over h2 (slot 12).
__device__ __forceinline__ void y_partial(float* sw, int b0, int q)
{
    const ulonglong2* h2  = (const ulonglong2*)(g_h + 2 * HQ * Bx);
    const ulonglong2* wy2 = (const ulonglong2*)(sw + WYOF);
    unsigned long long a0 = 0ULL, a1 = 0ULL;
    const int k0 = q * 8;
#pragma unroll
    for (int k4 = k0; k4 < k0 + 8; k4++) {
        ulonglong2 w  = wy2[k4];
        ulonglong2 h0 = h2[k4 * Bx + b0];
        ulonglong2 h1 = h2[k4 * Bx + b0 + 32];
        a0 = pfma(h0.x, w.x, a0);
        a1 = pfma(h1.x, w.x, a1);
        a0 = pfma(h0.y, w.y, a0);
        a1 = pfma(h1.y, w.y, a1);
    }
    sw[SM_RED + (q * 16 + 12) * Bx + b0]      = phsum(a0);
    sw[SM_RED + (q * 16 + 12) * Bx + b0 + 32] = phsum(a1);
}

__device__ __forceinline__ void y_final(float* sw, int lane, int cta,
                                        float* __restrict__ out, int tdst)
{
#pragma unroll
    for (int r = 0; r < 2; r++) {
        const int b = lane + 32 * r;
        float s = 0.f;
#pragma unroll
        for (int qq = 0; qq < 16; qq++)
            s += sw[SM_RED + (qq * 16 + 12) * Bx + b];
        out[((size_t)b * Sx + tdst) * Ox + cta] = s + sw[SM_BY];
    }
}

// ---------------------------------------------------------------------------
__global__ void init_kernel(const float* __restrict__ in, const float* __restrict__ hs)
{
    size_t i = (size_t)blockIdx.x * blockDim.x + threadIdx.x;
    size_t stride = (size_t)gridDim.x * blockDim.x;
    if (i == 0) g_bar = 0;

    for (size_t idx = i; idx < (size_t)Bx * Lx * Hx; idx += stride) {
        int b = (int)(idx / (Lx * Hx));
        int l = (int)((idx / Hx) % Lx);
        int k = (int)(idx % Hx);
        ((float*)g_h)[(((size_t)l * HQ + (k >> 2)) * Bx + b) * 4 + (k & 3)] = hs[idx];
    }
    for (size_t idx = i; idx < (size_t)Bx * Sx * Ix; idx += stride) {
        int b = (int)(idx / ((size_t)Sx * Ix));
        int s = (int)((idx / Ix) % Sx);
        int j = (int)(idx % Ix);
        ((float*)g_x0t)[(((size_t)s * IQ + (j >> 2)) * Bx + b) * 4 + (j & 3)] = in[idx];
    }
}

__global__ void __launch_bounds__(NTHR, 1) gru_main(
    const float* __restrict__ Wx0z, const float* __restrict__ Wx0r, const float* __restrict__ Wx0g,
    const float* __restrict__ Wxz,  const float* __restrict__ Wxr,  const float* __restrict__ Wxg,
    const float* __restrict__ Whz,  const float* __restrict__ Whr,  const float* __restrict__ Whg,
    const float* __restrict__ bz,   const float* __restrict__ br,   const float* __restrict__ bg,
    const float* __restrict__ Wy,   const float* __restrict__ by,
    float* __restrict__ out)
{
    extern __shared__ float sw[];
    const int tid = threadIdx.x;
    const int cta = blockIdx.x;
    const int nb  = cta * CPT;

    // ---- load this CTA's weight slices into SMEM (once) ----
    for (int i = tid; i < CPT * Hx; i += NTHR) {
        int cp = i >> 9, k = i & 511;
        int row = nb + cp;
        sw[WHZ0 + i] = Whz[((size_t)(0 * Hx + row)) * Hx + k];
        sw[WHR0 + i] = Whr[((size_t)(0 * Hx + row)) * Hx + k];
        sw[WHG0 + i] = Whg[((size_t)(0 * Hx + row)) * Hx + k];
        sw[WHZ1 + i] = Whz[((size_t)(1 * Hx + row)) * Hx + k];
        sw[WHR1 + i] = Whr[((size_t)(1 * Hx + row)) * Hx + k];
        sw[WHG1 + i] = Whg[((size_t)(1 * Hx + row)) * Hx + k];
        sw[WHZ2 + i] = Whz[((size_t)(2 * Hx + row)) * Hx + k];
        sw[WHR2 + i] = Whr[((size_t)(2 * Hx + row)) * Hx + k];
        sw[WHG2 + i] = Whg[((size_t)(2 * Hx + row)) * Hx + k];
        sw[WXZ1 + i] = Wxz[((size_t)(0 * Hx + row)) * Hx + k];
        sw[WXR1 + i] = Wxr[((size_t)(0 * Hx + row)) * Hx + k];
        sw[WXG1 + i] = Wxg[((size_t)(0 * Hx + row)) * Hx + k];
        sw[WXZ2 + i] = Wxz[((size_t)(1 * Hx + row)) * Hx + k];
        sw[WXR2 + i] = Wxr[((size_t)(1 * Hx + row)) * Hx + k];
        sw[WXG2 + i] = Wxg[((size_t)(1 * Hx + row)) * Hx + k];
    }
    for (int i = tid; i < CPT * Ix; i += NTHR) {
        int cp = i >> 7, j = i & 127;
        int row = nb + cp;
        sw[WX0Z + i] = Wx0z[(size_t)row * Ix + j];
        sw[WX0R + i] = Wx0r[(size_t)row * Ix + j];
        sw[WX0G + i] = Wx0g[(size_t)row * Ix + j];
    }
    for (int i = tid; i < Hx; i += NTHR)
        sw[WYOF + i] = Wy[(size_t)cta * Hx + i];
    if (tid < 12) {
        int l = tid >> 2, cp = tid & 3;
        sw[SM_BZ + tid] = bz[l * Hx + nb + cp];
        sw[SM_BR + tid] = br[l * Hx + nb + cp];
        sw[SM_BG + tid] = bg[l * Hx + nb + cp];
    }
    if (tid == 0) sw[SM_BY] = by[cta];
    __syncthreads();

    const int lane = tid & 31;
    const int q    = tid >> 5;     // 16 k-slices
    const int hb   = q * 8;        // h/rh float4 base
    const int xb0  = q * 2;        // layer-0 x float4 base

    const ulonglong2* h0u = (const ulonglong2*)(g_h);
    const ulonglong2* h1u = (const ulonglong2*)(g_h + 1 * HQ * Bx);
    const ulonglong2* h2u = (const ulonglong2*)(g_h + 2 * HQ * Bx);
    const ulonglong2* rhu = (const ulonglong2*)g_rh;

    const ulonglong2* wz0p = (const ulonglong2*)(sw + WHZ0);
    const ulonglong2* wr0p = (const ulonglong2*)(sw + WHR0);
    const ulonglong2* wg0p = (const ulonglong2*)(sw + WHG0);
    const ulonglong2* x0zp = (const ulonglong2*)(sw + WX0Z);
    const ulonglong2* x0rp = (const ulonglong2*)(sw + WX0R);
    const ulonglong2* x0gp = (const ulonglong2*)(sw + WX0G);
    const ulonglong2* wz1p = (const ulonglong2*)(sw + WHZ1);
    const ulonglong2* wr1p = (const ulonglong2*)(sw + WHR1);
    const ulonglong2* wg1p = (const ulonglong2*)(sw + WHG1);
    const ulonglong2* x1zp = (const ulonglong2*)(sw + WXZ1);
    const ulonglong2* x1rp = (const ulonglong2*)(sw + WXR1);
    const ulonglong2* x1gp = (const ulonglong2*)(sw + WXG1);
    const ulonglong2* wz2p = (const ulonglong2*)(sw + WHZ2);
    const ulonglong2* wr2p = (const ulonglong2*)(sw + WHR2);
    const ulonglong2* wg2p = (const ulonglong2*)(sw + WHG2);
    const ulonglong2* x2zp = (const ulonglong2*)(sw + WXZ2);
    const ulonglong2* x2rp = (const ulonglong2*)(sw + WXR2);
    const ulonglong2* x2gp = (const ulonglong2*)(sw + WXG2);

    float2 z_reg = make_float2(0.f, 0.f), xg_reg = make_float2(0.f, 0.f);
    unsigned bv = 0;

    unsigned long long az[2][4], ar[2][4], ag[2][4];

    // Prologue: layer-0 h-dots for t=0 (initial h0 state, no barrier needed).
    zero24(az, ar, ag);
    dacc2<8>(az, ar, h0u, hb, lane, wz0p, wr0p, 128);

    for (int t = 0; t < Sx; t++) {
        const ulonglong2* xt = (const ulonglong2*)(g_x0t + (size_t)t * IQ * Bx);

        // ---- P(0,1): x-dots (static input) overlap bar5 wait ----
        dacc3<2>(az, ar, ag, xt, xb0, lane, x0zp, x0rp, x0gp, 32);
        if (t > 0) gbar_wait(bv * NCTA);          // bar5 of prev step
        store_zrg(sw, q, lane, az, ar, ag);
        if (t > 0) y_partial(sw, lane, q);        // h2_new visible after bar5
        __syncthreads();
        p1_final(sw, lane, q, cta, 0, (const float*)g_h, z_reg, xg_reg);
        if (t > 0 && q == 4) y_final(sw, lane, cta, out, t - 1);
        gbar_arrive(); bv++;                      // bar0

        // ---- overlap bar0: P(1,1) h-dots (h1 old state) ----
        zero24(az, ar, ag);
        dacc2<8>(az, ar, h1u, hb, lane, wz1p, wr1p, 128);
        gbar_wait(bv * NCTA);                     // bar0: rh0 ready

        // ---- P(0,2) ----
        {
            unsigned long long a[2][4];
            zero8(a);
            dacc1<8>(a, rhu, hb, lane, wg0p, 128);
            store_g(sw, q, lane, a);
        }
        __syncthreads();
        p2_final(sw, lane, q, cta, 0, z_reg, xg_reg);
        gbar_arrive(); bv++;                      // bar1
        gbar_wait(bv * NCTA);                     // bar1: h0_new ready (unhidden)

        // ---- P(1,1) x-dots (x = h0_new), merge into held z/r ----
        dacc3<8>(az, ar, ag, h0u, hb, lane, x1zp, x1rp, x1gp, 128);
        store_zrg(sw, q, lane, az, ar, ag);
        __syncthreads();
        p1_final(sw, lane, q, cta, 1, (const float*)(g_h + HQ * Bx), z_reg, xg_reg);
        gbar_arrive(); bv++;                      // bar2
        gbar_wait(bv * NCTA);                     // bar2: rh1 ready (unhidden)

        // ---- P(1,2) ----
        {
            unsigned long long a[2][4];
            zero8(a);
            dacc1<8>(a, rhu, hb, lane, wg1p, 128);
            store_g(sw, q, lane, a);
        }
        __syncthreads();
        p2_final(sw, lane, q, cta, 1, z_reg, xg_reg);
        gbar_arrive(); bv++;                      // bar3

        // ---- overlap bar3: P(2,1) h-dots (h2 old state) ----
        zero24(az, ar, ag);
        dacc2<8>(az, ar, h2u, hb, lane, wz2p, wr2p, 128);
        gbar_wait(bv * NCTA);                     // bar3: h1_new ready

        // ---- P(2,1) x-dots (x = h1_new) ----
        dacc3<8>(az, ar, ag, h1u, hb, lane, x2zp, x2rp, x2gp, 128);
        store_zrg(sw, q, lane, az, ar, ag);
        __syncthreads();
        p1_final(sw, lane, q, cta, 2, (const float*)(g_h + 2 * HQ * Bx), z_reg, xg_reg);
        gbar_arrive(); bv++;                      // bar4

        // ---- overlap bar4: next-step P(0,1) h0-dots (h0_new global since bar2) ----
        zero24(az, ar, ag);
        dacc2<8>(az, ar, h0u, hb, lane, wz0p, wr0p, 128);
        gbar_wait(bv * NCTA);                     // bar4: rh2 ready

        // ---- P(2,2) ----
        {
            unsigned long long a[2][4];
            zero8(a);
            dacc1<8>(a, rhu, hb, lane, wg2p, 128);
            store_g(sw, q, lane, a);
        }
        __syncthreads();
        p2_final(sw, lane, q, cta, 2, z_reg, xg_reg);
        gbar_arrive(); bv++;                      // bar5 (waited at top of next t)
    }

    // Epilogue: y for the final timestep.
    gbar_wait(bv * NCTA);                         // bar5 of last step
    y_partial(sw, lane, q);
    __syncthreads();
    if (q == 4) y_final(sw, lane, cta, out, Sx - 1);

    // hidden_out (B, L, H)
    if (q < 4) {
        const int c = q;
#pragma unroll
        for (int r = 0; r < 2; r++) {
            const int b = lane + 32 * r;
#pragma unroll
            for (int l = 0; l < Lx; l++) {
                float hv = ((const float*)g_h)[(((size_t)l * HQ + cta) * Bx + b) * 4 + c];
                out[(size_t)Bx * Sx * Ox + ((size_t)b * Lx + l) * Hx + nb + c] = hv;
            }
        }
    }
}

// ---------------------------------------------------------------------------
extern "C" void kernel_launch(void* const* d_in, const int* in_sizes, int n_in,
                              void* d_out, int out_size)
{
    const float* input = (const float*)d_in[0];
    const float* hs    = (const float*)d_in[1];
    const float* Wx0z  = (const float*)d_in[2];
    const float* Wx0r  = (const float*)d_in[3];
    const float* Wx0g  = (const float*)d_in[4];
    const float* Wxz   = (const float*)d_in[5];
    const float* Wxr   = (const float*)d_in[6];
    const float* Wxg   = (const float*)d_in[7];
    const float* Whz   = (const float*)d_in[8];
    const float* Whr   = (const float*)d_in[9];
    const float* Whg   = (const float*)d_in[10];
    const float* bz    = (const float*)d_in[11];
    const float* br    = (const float*)d_in[12];
    const float* bg    = (const float*)d_in[13];
    const float* Wy    = (const float*)d_in[14];
    const float* by    = (const float*)d_in[15];
    float* out = (float*)d_out;

    cudaFuncSetAttribute(gru_main, cudaFuncAttributeMaxDynamicSharedMemorySize, SMEM_BYTES);

    init_kernel<<<1024, 256>>>(input, hs);
    gru_main<<<NCTA, NTHR, SMEM_BYTES>>>(Wx0z, Wx0r, Wx0g, Wxz, Wxr, Wxg,
                                         Whz, Whr, Whg, bz, br, bg, Wy, by, out);
}